// round 2
// baseline (speedup 1.0000x reference)
#include <cuda_runtime.h>
#include <math.h>

#define NTOK 2048
#define DIM  2048
#define NEXP 64
#define TOPK 8
#define FFN  768
#define CAP  512   // = 2 * NTOK*TOPK / NEXP, matches reference capacity

// ---------------- device scratch (static, allocation-free) ----------------
__device__ int   g_counts[NEXP];
__device__ int   g_tok[NEXP * CAP];
__device__ float g_score[NEXP * CAP];
__device__ int   g_loc[NTOK * TOPK];
__device__ float g_H[(size_t)NEXP * CAP * FFN];   // ~100 MB
__device__ float g_Y[(size_t)NEXP * CAP * DIM];   // ~268 MB

// ---------------- packed f32x2 helpers (sm_103a FFMA2) ----------------
static __device__ __forceinline__ unsigned long long fma2(unsigned long long a,
                                                          unsigned long long b,
                                                          unsigned long long c) {
    asm("fma.rn.f32x2 %0, %1, %2, %0;" : "+l"(c) : "l"(a), "l"(b));
    return c;
}
static __device__ __forceinline__ unsigned long long pack2(float x) {
    unsigned long long r;
    asm("mov.b64 %0, {%1, %1};" : "=l"(r) : "f"(x));
    return r;
}
static __device__ __forceinline__ float2 unpk(unsigned long long v) {
    float2 f;
    asm("mov.b64 {%0, %1}, %2;" : "=f"(f.x), "=f"(f.y) : "l"(v));
    return f;
}

// ---------------- kernel 0: zero expert counters ----------------
__global__ void k_zero_counts() {
    if (threadIdx.x < NEXP) g_counts[threadIdx.x] = 0;
}

// ---------------- kernel 1: gating (logits -> softmax -> top8 -> route) ---
__global__ void __launch_bounds__(128) k_gating(const float* __restrict__ x,
                                                const float* __restrict__ gw) {
    int t = blockIdx.x;
    __shared__ float4 xs4[DIM / 4];
    __shared__ float prob[NEXP];

    int tid = threadIdx.x, lane = tid & 31, warp = tid >> 5;
    const float4* xg = (const float4*)(x + (size_t)t * DIM);
    for (int i = tid; i < DIM / 4; i += 128) xs4[i] = xg[i];
    __syncthreads();

    // 4 warps x 16 experts each: warp-dot over D
    for (int e = 0; e < 16; e++) {
        int ex = warp * 16 + e;
        const float4* g4 = (const float4*)(gw + (size_t)ex * DIM);
        float s = 0.f;
        for (int j = lane; j < DIM / 4; j += 32) {
            float4 a = g4[j];
            float4 b = xs4[j];
            s += a.x * b.x + a.y * b.y + a.z * b.z + a.w * b.w;
        }
        #pragma unroll
        for (int o = 16; o > 0; o >>= 1) s += __shfl_down_sync(0xffffffffu, s, o);
        if (lane == 0) prob[ex] = s;   // logits for now
    }
    __syncthreads();

    if (warp == 0) {
        float l0 = prob[lane], l1 = prob[lane + 32];
        float m = fmaxf(l0, l1);
        #pragma unroll
        for (int o = 16; o > 0; o >>= 1) m = fmaxf(m, __shfl_xor_sync(0xffffffffu, m, o));
        float p0 = expf(l0 - m), p1 = expf(l1 - m);
        float z = p0 + p1;
        #pragma unroll
        for (int o = 16; o > 0; o >>= 1) z += __shfl_xor_sync(0xffffffffu, z, o);
        float inv = 1.f / z;
        prob[lane] = p0 * inv;
        prob[lane + 32] = p1 * inv;
        __syncwarp();

        // iterative top-8; tie-break = lowest index (matches jax.lax.top_k)
        for (int k = 0; k < TOPK; k++) {
            float v0 = prob[lane], v1 = prob[lane + 32];
            float bv = v0; int bi = lane;
            if (v1 > v0) { bv = v1; bi = lane + 32; }
            #pragma unroll
            for (int o = 16; o > 0; o >>= 1) {
                float ov = __shfl_down_sync(0xffffffffu, bv, o);
                int   oi = __shfl_down_sync(0xffffffffu, bi, o);
                if (ov > bv || (ov == bv && oi < bi)) { bv = ov; bi = oi; }
            }
            if (lane == 0) {
                int e = bi;
                float s = prob[bi];
                int slot = atomicAdd(&g_counts[e], 1);
                int loc = -1;
                if (slot < CAP) {
                    loc = e * CAP + slot;
                    g_tok[loc] = t;
                    g_score[loc] = s;
                }
                g_loc[t * TOPK + k] = loc;
                prob[bi] = -1.f;
            }
            __syncwarp();
        }
    }
}

// ---------------- kernel 2: grouped GEMM1 (gate+up) + SwiGLU -> H ---------
// tiles: BM=128 (pairs), BN=64 (F), BK=16. micro: 8m x 4n per matrix.
__global__ void __launch_bounds__(256) k_ffn1(const float* __restrict__ x,
                                              const float* __restrict__ wg,
                                              const float* __restrict__ wu) {
    int e = blockIdx.z;
    int cnt = min(g_counts[e], CAP);
    int m0 = blockIdx.y * 128;
    if (m0 >= cnt) return;
    int n0 = blockIdx.x * 64;

    __shared__ float As[128 * 17];
    __shared__ float Bg[16 * 64];
    __shared__ float Bu[16 * 64];

    int tid = threadIdx.x;
    int tn = tid & 15, tm = tid >> 4;

    // A-load mapping: rows lr0 and lr0+64, 4 contiguous k (kg)
    int lr0 = tid >> 2;
    int kg  = (tid & 3) * 4;
    const float* a0 = nullptr;
    const float* a1 = nullptr;
    {
        int r = m0 + lr0;
        if (r < cnt) a0 = x + (size_t)g_tok[e * CAP + r] * DIM;
        r = m0 + lr0 + 64;
        if (r < cnt) a1 = x + (size_t)g_tok[e * CAP + r] * DIM;
    }
    // B-load mapping: one f-row per 4 threads
    int bn = tid >> 2;
    const float* bgp = wg + (size_t)e * FFN * DIM + (size_t)(n0 + bn) * DIM + kg;
    const float* bup = wu + (size_t)e * FFN * DIM + (size_t)(n0 + bn) * DIM + kg;

    unsigned long long aG[8][2] = {};
    unsigned long long aU[8][2] = {};

    for (int kk = 0; kk < DIM; kk += 16) {
        float4 va = a0 ? *(const float4*)(a0 + kk + kg) : make_float4(0.f, 0.f, 0.f, 0.f);
        float4 vb = a1 ? *(const float4*)(a1 + kk + kg) : make_float4(0.f, 0.f, 0.f, 0.f);
        float4 vg = *(const float4*)(bgp + kk);
        float4 vu = *(const float4*)(bup + kk);
        __syncthreads();
        As[lr0 * 17 + kg + 0] = va.x; As[lr0 * 17 + kg + 1] = va.y;
        As[lr0 * 17 + kg + 2] = va.z; As[lr0 * 17 + kg + 3] = va.w;
        As[(lr0 + 64) * 17 + kg + 0] = vb.x; As[(lr0 + 64) * 17 + kg + 1] = vb.y;
        As[(lr0 + 64) * 17 + kg + 2] = vb.z; As[(lr0 + 64) * 17 + kg + 3] = vb.w;
        Bg[(kg + 0) * 64 + bn] = vg.x; Bg[(kg + 1) * 64 + bn] = vg.y;
        Bg[(kg + 2) * 64 + bn] = vg.z; Bg[(kg + 3) * 64 + bn] = vg.w;
        Bu[(kg + 0) * 64 + bn] = vu.x; Bu[(kg + 1) * 64 + bn] = vu.y;
        Bu[(kg + 2) * 64 + bn] = vu.z; Bu[(kg + 3) * 64 + bn] = vu.w;
        __syncthreads();

        #pragma unroll
        for (int k = 0; k < 16; k++) {
            unsigned long long bg0 = *(const unsigned long long*)&Bg[k * 64 + tn * 4];
            unsigned long long bg1 = *(const unsigned long long*)&Bg[k * 64 + tn * 4 + 2];
            unsigned long long bu0 = *(const unsigned long long*)&Bu[k * 64 + tn * 4];
            unsigned long long bu1 = *(const unsigned long long*)&Bu[k * 64 + tn * 4 + 2];
            #pragma unroll
            for (int i = 0; i < 8; i++) {
                unsigned long long ap = pack2(As[(tm * 8 + i) * 17 + k]);
                aG[i][0] = fma2(ap, bg0, aG[i][0]);
                aG[i][1] = fma2(ap, bg1, aG[i][1]);
                aU[i][0] = fma2(ap, bu0, aU[i][0]);
                aU[i][1] = fma2(ap, bu1, aU[i][1]);
            }
        }
    }

    // epilogue: h = silu(g) * u
    #pragma unroll
    for (int i = 0; i < 8; i++) {
        int row = m0 + tm * 8 + i;
        float2 g0 = unpk(aG[i][0]), g1 = unpk(aG[i][1]);
        float2 u0 = unpk(aU[i][0]), u1 = unpk(aU[i][1]);
        float4 h;
        h.x = g0.x / (1.f + expf(-g0.x)) * u0.x;
        h.y = g0.y / (1.f + expf(-g0.y)) * u0.y;
        h.z = g1.x / (1.f + expf(-g1.x)) * u1.x;
        h.w = g1.y / (1.f + expf(-g1.y)) * u1.y;
        *(float4*)&g_H[((size_t)e * CAP + row) * FFN + n0 + tn * 4] = h;
    }
}

// ---------------- kernel 3: grouped GEMM2 (H @ w_down^T) * score -> Y -----
// tiles: BM=128, BN=128 (D), BK=16, K=768. micro: 8m x 8n.
__global__ void __launch_bounds__(256) k_ffn2(const float* __restrict__ wd) {
    int e = blockIdx.z;
    int cnt = min(g_counts[e], CAP);
    int m0 = blockIdx.y * 128;
    if (m0 >= cnt) return;
    int n0 = blockIdx.x * 128;

    __shared__ float As[128 * 17];
    __shared__ float Bs[16 * 128];

    int tid = threadIdx.x;
    int tn = tid & 15, tm = tid >> 4;
    int lr = tid >> 2;
    int kg = (tid & 3) * 4;

    const float* h0 = g_H + ((size_t)e * CAP + m0 + lr) * FFN + kg;
    const float* h1 = h0 + (size_t)64 * FFN;
    const float* b0 = wd + (size_t)e * DIM * FFN + (size_t)(n0 + lr) * FFN + kg;
    const float* b1 = b0 + (size_t)64 * FFN;

    unsigned long long acc[8][4] = {};

    for (int kk = 0; kk < FFN; kk += 16) {
        float4 va = *(const float4*)(h0 + kk);
        float4 vb = *(const float4*)(h1 + kk);
        float4 w0 = *(const float4*)(b0 + kk);
        float4 w1 = *(const float4*)(b1 + kk);
        __syncthreads();
        As[lr * 17 + kg + 0] = va.x; As[lr * 17 + kg + 1] = va.y;
        As[lr * 17 + kg + 2] = va.z; As[lr * 17 + kg + 3] = va.w;
        As[(lr + 64) * 17 + kg + 0] = vb.x; As[(lr + 64) * 17 + kg + 1] = vb.y;
        As[(lr + 64) * 17 + kg + 2] = vb.z; As[(lr + 64) * 17 + kg + 3] = vb.w;
        Bs[(kg + 0) * 128 + lr] = w0.x; Bs[(kg + 1) * 128 + lr] = w0.y;
        Bs[(kg + 2) * 128 + lr] = w0.z; Bs[(kg + 3) * 128 + lr] = w0.w;
        Bs[(kg + 0) * 128 + lr + 64] = w1.x; Bs[(kg + 1) * 128 + lr + 64] = w1.y;
        Bs[(kg + 2) * 128 + lr + 64] = w1.z; Bs[(kg + 3) * 128 + lr + 64] = w1.w;
        __syncthreads();

        #pragma unroll
        for (int k = 0; k < 16; k++) {
            unsigned long long bb0 = *(const unsigned long long*)&Bs[k * 128 + tn * 8];
            unsigned long long bb1 = *(const unsigned long long*)&Bs[k * 128 + tn * 8 + 2];
            unsigned long long bb2 = *(const unsigned long long*)&Bs[k * 128 + tn * 8 + 4];
            unsigned long long bb3 = *(const unsigned long long*)&Bs[k * 128 + tn * 8 + 6];
            #pragma unroll
            for (int i = 0; i < 8; i++) {
                unsigned long long ap = pack2(As[(tm * 8 + i) * 17 + k]);
                acc[i][0] = fma2(ap, bb0, acc[i][0]);
                acc[i][1] = fma2(ap, bb1, acc[i][1]);
                acc[i][2] = fma2(ap, bb2, acc[i][2]);
                acc[i][3] = fma2(ap, bb3, acc[i][3]);
            }
        }
    }

    #pragma unroll
    for (int i = 0; i < 8; i++) {
        int row = m0 + tm * 8 + i;
        float s = g_score[e * CAP + row];   // garbage rows >= cnt are never gathered
        float2 y0 = unpk(acc[i][0]), y1 = unpk(acc[i][1]);
        float2 y2 = unpk(acc[i][2]), y3 = unpk(acc[i][3]);
        float4 o0 = make_float4(y0.x * s, y0.y * s, y1.x * s, y1.y * s);
        float4 o1 = make_float4(y2.x * s, y2.y * s, y3.x * s, y3.y * s);
        float* dst = &g_Y[((size_t)e * CAP + row) * DIM + n0 + tn * 8];
        *(float4*)dst = o0;
        *(float4*)(dst + 4) = o1;
    }
}

// ---------------- kernel 4: combine (gather-sum 8 pairs per token) --------
__global__ void __launch_bounds__(256) k_combine(float* __restrict__ out) {
    int t = blockIdx.x;
    int tid = threadIdx.x;
    float4 a0 = make_float4(0.f, 0.f, 0.f, 0.f);
    float4 a1 = make_float4(0.f, 0.f, 0.f, 0.f);
    #pragma unroll
    for (int k = 0; k < TOPK; k++) {
        int loc = g_loc[t * TOPK + k];
        if (loc < 0) continue;
        const float4* y = (const float4*)(g_Y + (size_t)loc * DIM);
        float4 v0 = y[tid * 2], v1 = y[tid * 2 + 1];
        a0.x += v0.x; a0.y += v0.y; a0.z += v0.z; a0.w += v0.w;
        a1.x += v1.x; a1.y += v1.y; a1.z += v1.z; a1.w += v1.w;
    }
    float4* o = (float4*)(out + (size_t)t * DIM);
    o[tid * 2] = a0;
    o[tid * 2 + 1] = a1;
}

// ---------------- launch ----------------
extern "C" void kernel_launch(void* const* d_in, const int* in_sizes, int n_in,
                              void* d_out, int out_size) {
    const float* x   = (const float*)d_in[0];   // hidden_states [1,2048,2048]
    const float* gw  = (const float*)d_in[1];   // gate_w  [64,2048]
    const float* wg  = (const float*)d_in[2];   // w_gate  [64,768,2048]
    const float* wu  = (const float*)d_in[3];   // w_up    [64,768,2048]
    const float* wd  = (const float*)d_in[4];   // w_down  [64,2048,768]
    float* out = (float*)d_out;

    k_zero_counts<<<1, 64>>>();
    k_gating<<<NTOK, 128>>>(x, gw);
    k_ffn1<<<dim3(FFN / 64, CAP / 128, NEXP), 256>>>(x, wg, wu);
    k_ffn2<<<dim3(DIM / 128, CAP / 128, NEXP), 256>>>(wd);
    k_combine<<<NTOK, 256>>>(out);
}

// round 5
// speedup vs baseline: 2.1535x; 2.1535x over previous
#include <cuda_runtime.h>
#include <cuda_bf16.h>
#include <stdint.h>
#include <math.h>

#define NTOK 2048
#define DIM  2048
#define NEXP 64
#define TOPK 8
#define FFN  768
#define CAP  512

// ---------------- device scratch ----------------
__device__ int   g_counts[NEXP];
__device__ int   g_tok[NEXP * CAP];
__device__ float g_score[NEXP * CAP];
__device__ int   g_loc[NTOK * TOPK];
__device__ __align__(16) __nv_bfloat16 g_xhi[(size_t)NTOK * DIM];
__device__ __align__(16) __nv_bfloat16 g_xlo[(size_t)NTOK * DIM];
__device__ __align__(16) __nv_bfloat16 g_Hhi[(size_t)NEXP * CAP * FFN];
__device__ __align__(16) __nv_bfloat16 g_Hlo[(size_t)NEXP * CAP * FFN];
__device__ __align__(16) float g_Y[(size_t)NEXP * CAP * DIM];

// ---------------- helpers ----------------
static __device__ __forceinline__ uint32_t smem_u32(const void* p) {
    uint32_t a;
    asm("{ .reg .u64 t; cvta.to.shared.u64 t, %1; cvt.u32.u64 %0, t; }" : "=r"(a) : "l"(p));
    return a;
}
static __device__ __forceinline__ void cpasync16(uint32_t s, const void* g) {
    asm volatile("cp.async.ca.shared.global [%0], [%1], 16;" :: "r"(s), "l"(g));
}
#define CP_COMMIT() asm volatile("cp.async.commit_group;" ::: "memory")
#define CP_WAIT0()  asm volatile("cp.async.wait_group 0;" ::: "memory")

// mma.sync m16n8k16 bf16 -> f32 (sm_80 feature set; valid on plain sm_103)
static __device__ __forceinline__ void mma16816(float* c, const uint32_t* a, const uint32_t* b) {
    asm volatile("mma.sync.aligned.m16n8k16.row.col.f32.bf16.bf16.f32 "
        "{%0,%1,%2,%3}, {%4,%5,%6,%7}, {%8,%9}, {%0,%1,%2,%3};"
        : "+f"(c[0]), "+f"(c[1]), "+f"(c[2]), "+f"(c[3])
        : "r"(a[0]), "r"(a[1]), "r"(a[2]), "r"(a[3]), "r"(b[0]), "r"(b[1]));
}

// fp32 -> bf16 hi + bf16 lo (pairwise packed in b32)
static __device__ __forceinline__ void cvt2(float a0, float a1, uint32_t& hi2, uint32_t& lo2) {
    asm("cvt.rn.bf16x2.f32 %0, %1, %2;" : "=r"(hi2) : "f"(a1), "f"(a0));
    float h0 = __uint_as_float(hi2 << 16);
    float h1 = __uint_as_float(hi2 & 0xffff0000u);
    float l0 = a0 - h0, l1 = a1 - h1;
    asm("cvt.rn.bf16x2.f32 %0, %1, %2;" : "=r"(lo2) : "f"(l1), "f"(l0));
}
static __device__ __forceinline__ void hilo8(float4 a, float4 b, uint4& hi, uint4& lo) {
    cvt2(a.x, a.y, hi.x, lo.x);
    cvt2(a.z, a.w, hi.y, lo.y);
    cvt2(b.x, b.y, hi.z, lo.z);
    cvt2(b.z, b.w, hi.w, lo.w);
}
static __device__ __forceinline__ uint32_t ld32s(const uint16_t* p) {
    return *(const uint32_t*)p;
}

// ---------------- kernel 0: zero counters ----------------
__global__ void k_zero_counts() {
    if (threadIdx.x < NEXP) g_counts[threadIdx.x] = 0;
}

// ---------------- kernel 1: split x into bf16 hi/lo ----------------
__global__ void __launch_bounds__(256) k_xsplit(const float* __restrict__ x) {
    size_t base = ((size_t)blockIdx.x * 256 + threadIdx.x) * 8;
    float4 a = *(const float4*)(x + base);
    float4 b = *(const float4*)(x + base + 4);
    uint4 hi, lo;
    hilo8(a, b, hi, lo);
    *(uint4*)((uint16_t*)g_xhi + base) = hi;
    *(uint4*)((uint16_t*)g_xlo + base) = lo;
}

// ---------------- kernel 2: gating ----------------
__global__ void __launch_bounds__(128) k_gating(const float* __restrict__ x,
                                                const float* __restrict__ gw) {
    int t = blockIdx.x;
    __shared__ float4 xs4[DIM / 4];
    __shared__ float prob[NEXP];

    int tid = threadIdx.x, lane = tid & 31, warp = tid >> 5;
    const float4* xg = (const float4*)(x + (size_t)t * DIM);
    for (int i = tid; i < DIM / 4; i += 128) xs4[i] = xg[i];
    __syncthreads();

    for (int e = 0; e < 16; e++) {
        int ex = warp * 16 + e;
        const float4* g4 = (const float4*)(gw + (size_t)ex * DIM);
        float s = 0.f;
        for (int j = lane; j < DIM / 4; j += 32) {
            float4 a = g4[j];
            float4 b = xs4[j];
            s += a.x * b.x + a.y * b.y + a.z * b.z + a.w * b.w;
        }
        #pragma unroll
        for (int o = 16; o > 0; o >>= 1) s += __shfl_down_sync(0xffffffffu, s, o);
        if (lane == 0) prob[ex] = s;
    }
    __syncthreads();

    if (warp == 0) {
        float l0 = prob[lane], l1 = prob[lane + 32];
        float m = fmaxf(l0, l1);
        #pragma unroll
        for (int o = 16; o > 0; o >>= 1) m = fmaxf(m, __shfl_xor_sync(0xffffffffu, m, o));
        float p0 = expf(l0 - m), p1 = expf(l1 - m);
        float z = p0 + p1;
        #pragma unroll
        for (int o = 16; o > 0; o >>= 1) z += __shfl_xor_sync(0xffffffffu, z, o);
        float inv = 1.f / z;
        prob[lane] = p0 * inv;
        prob[lane + 32] = p1 * inv;
        __syncwarp();

        for (int k = 0; k < TOPK; k++) {
            float v0 = prob[lane], v1 = prob[lane + 32];
            float bv = v0; int bi = lane;
            if (v1 > v0) { bv = v1; bi = lane + 32; }
            #pragma unroll
            for (int o = 16; o > 0; o >>= 1) {
                float ov = __shfl_down_sync(0xffffffffu, bv, o);
                int   oi = __shfl_down_sync(0xffffffffu, bi, o);
                if (ov > bv || (ov == bv && oi < bi)) { bv = ov; bi = oi; }
            }
            if (lane == 0) {
                int e = bi;
                float s = prob[bi];
                int slot = atomicAdd(&g_counts[e], 1);
                int loc = -1;
                if (slot < CAP) {
                    loc = e * CAP + slot;
                    g_tok[loc] = t;
                    g_score[loc] = s;
                }
                g_loc[t * TOPK + k] = loc;
                prob[bi] = -1.f;
            }
            __syncwarp();
        }
    }
}

// ====================== GEMM smem layout (halves) ======================
// Stage = 20480 halves = 40960 B; two stages = 81920 B dynamic smem.
#define SROW 40          // smem row stride in halves (conflict-free for frags)
#define STAGE_H 20480
#define SMEM_BYTES (2 * STAGE_H * 2)

// GEMM1 regions (halves within a stage)
#define S1_AH 0
#define S1_AL 5120
#define S1_GH 10240
#define S1_GL 12800
#define S1_UH 15360
#define S1_UL 17920

// GEMM2 regions
#define S2_AH 0
#define S2_AL 5120
#define S2_BH 10240
#define S2_BL 15360

// ---------------- kernel 3: grouped GEMM1 (gate+up) + SwiGLU -> Hhi/Hlo ----
// BM=128 (pair rows), BN=64 (ffn cols, both matrices), BK=32, 3-pass bf16.
__global__ void __launch_bounds__(256, 1) k_ffn1_mma(const float* __restrict__ wg,
                                                     const float* __restrict__ wu) {
    extern __shared__ __align__(16) uint16_t sm[];
    const int e = blockIdx.z;
    const int cnt = min(g_counts[e], CAP);
    const int m0 = blockIdx.y * 128;
    if (m0 >= cnt) return;
    const int n0 = blockIdx.x * 64;
    const int tid = threadIdx.x;
    const uint32_t sbase = smem_u32(sm);

    // A (tokens, bf16 pre-split) via cp.async: row = tid>>1, 16-half seg = tid&1
    const int arow = tid >> 1, ak = (tid & 1) * 16;
    const int tr = m0 + arow;
    const int tok = (tr < cnt) ? g_tok[e * CAP + tr] : 0;
    const uint16_t* gah = (const uint16_t*)g_xhi + (size_t)tok * DIM + ak;
    const uint16_t* gal = (const uint16_t*)g_xlo + (size_t)tok * DIM + ak;
    const uint32_t sAoff = (uint32_t)(arow * SROW + ak) * 2;

    // B (weights fp32, convert in-reg): row = tid>>2 (0..63), k seg = (tid&3)*8
    const int brow = tid >> 2, bk = (tid & 3) * 8;
    const float* gbg = wg + (size_t)e * FFN * DIM + (size_t)(n0 + brow) * DIM + bk;
    const float* gbu = wu + (size_t)e * FFN * DIM + (size_t)(n0 + brow) * DIM + bk;
    const uint32_t bidx = (uint32_t)(brow * SROW + bk);

    const int wid = tid >> 5, lane = tid & 31;
    const int wm = wid >> 1, wn = wid & 1;
    const int fg = lane >> 2, ft = lane & 3;

    float cg[2][4][4] = {};
    float cu[2][4][4] = {};
    float4 rg0, rg1, ru0, ru1;

    // prologue: chunk 0
    {
        uint32_t d = sbase + sAoff;
        cpasync16(d, gah); cpasync16(d + 16, gah + 8);
        cpasync16(d + S1_AL * 2, gal); cpasync16(d + S1_AL * 2 + 16, gal + 8);
        CP_COMMIT();
        rg0 = *(const float4*)gbg; rg1 = *(const float4*)(gbg + 4);
        ru0 = *(const float4*)gbu; ru1 = *(const float4*)(gbu + 4);
    }

    const int C = DIM / 32;
    for (int c = 0; c < C; c++) {
        const int st = c & 1;
        uint16_t* S = sm + st * STAGE_H;
        CP_WAIT0();
        // store B (convert fp32 -> hi/lo)
        {
            uint4 hi, lo;
            hilo8(rg0, rg1, hi, lo);
            *(uint4*)&S[S1_GH + bidx] = hi;
            *(uint4*)&S[S1_GL + bidx] = lo;
            hilo8(ru0, ru1, hi, lo);
            *(uint4*)&S[S1_UH + bidx] = hi;
            *(uint4*)&S[S1_UL + bidx] = lo;
        }
        __syncthreads();
        if (c + 1 < C) {
            const int kk = (c + 1) * 32;
            uint32_t d = sbase + (uint32_t)(st ^ 1) * STAGE_H * 2 + sAoff;
            cpasync16(d, gah + kk); cpasync16(d + 16, gah + kk + 8);
            cpasync16(d + S1_AL * 2, gal + kk); cpasync16(d + S1_AL * 2 + 16, gal + kk + 8);
            CP_COMMIT();
            rg0 = *(const float4*)(gbg + kk); rg1 = *(const float4*)(gbg + kk + 4);
            ru0 = *(const float4*)(gbu + kk); ru1 = *(const float4*)(gbu + kk + 4);
        }
        // compute 2 k-steps
        #pragma unroll
        for (int ks = 0; ks < 2; ks++) {
            const int kb = ks * 16 + ft * 2;
            uint32_t ah[2][4], al[2][4];
            #pragma unroll
            for (int i = 0; i < 2; i++) {
                const int r = wm * 32 + i * 16 + fg;
                ah[i][0] = ld32s(&S[S1_AH + r * SROW + kb]);
                ah[i][1] = ld32s(&S[S1_AH + (r + 8) * SROW + kb]);
                ah[i][2] = ld32s(&S[S1_AH + r * SROW + kb + 8]);
                ah[i][3] = ld32s(&S[S1_AH + (r + 8) * SROW + kb + 8]);
                al[i][0] = ld32s(&S[S1_AL + r * SROW + kb]);
                al[i][1] = ld32s(&S[S1_AL + (r + 8) * SROW + kb]);
                al[i][2] = ld32s(&S[S1_AL + r * SROW + kb + 8]);
                al[i][3] = ld32s(&S[S1_AL + (r + 8) * SROW + kb + 8]);
            }
            uint32_t bgh[4][2], bgl[4][2], buh[4][2], bul[4][2];
            #pragma unroll
            for (int j = 0; j < 4; j++) {
                const int cb = (wn * 32 + j * 8 + fg) * SROW + ks * 16 + ft * 2;
                bgh[j][0] = ld32s(&S[S1_GH + cb]); bgh[j][1] = ld32s(&S[S1_GH + cb + 8]);
                bgl[j][0] = ld32s(&S[S1_GL + cb]); bgl[j][1] = ld32s(&S[S1_GL + cb + 8]);
                buh[j][0] = ld32s(&S[S1_UH + cb]); buh[j][1] = ld32s(&S[S1_UH + cb + 8]);
                bul[j][0] = ld32s(&S[S1_UL + cb]); bul[j][1] = ld32s(&S[S1_UL + cb + 8]);
            }
            #pragma unroll
            for (int i = 0; i < 2; i++)
                #pragma unroll
                for (int j = 0; j < 4; j++) {
                    mma16816(cg[i][j], ah[i], bgh[j]);
                    mma16816(cg[i][j], ah[i], bgl[j]);
                    mma16816(cg[i][j], al[i], bgh[j]);
                    mma16816(cu[i][j], ah[i], buh[j]);
                    mma16816(cu[i][j], ah[i], bul[j]);
                    mma16816(cu[i][j], al[i], buh[j]);
                }
        }
        __syncthreads();
    }

    // epilogue: h = silu(g)*u -> bf16 hi/lo
    uint16_t* hh = (uint16_t*)g_Hhi;
    uint16_t* hl = (uint16_t*)g_Hlo;
    const size_t ebase = (size_t)e * CAP;
    #pragma unroll
    for (int i = 0; i < 2; i++)
        #pragma unroll
        for (int j = 0; j < 4; j++) {
            const int r0 = m0 + wm * 32 + i * 16 + fg;
            const int col = n0 + wn * 32 + j * 8 + ft * 2;
            #pragma unroll
            for (int h = 0; h < 2; h++) {
                const int r = r0 + h * 8;
                float gv0 = cg[i][j][2 * h], gv1 = cg[i][j][2 * h + 1];
                float uv0 = cu[i][j][2 * h], uv1 = cu[i][j][2 * h + 1];
                float h0 = gv0 / (1.f + __expf(-gv0)) * uv0;
                float h1 = gv1 / (1.f + __expf(-gv1)) * uv1;
                uint32_t hi, lo;
                cvt2(h0, h1, hi, lo);
                *(uint32_t*)&hh[(ebase + r) * FFN + col] = hi;
                *(uint32_t*)&hl[(ebase + r) * FFN + col] = lo;
            }
        }
}

// ---------------- kernel 4: grouped GEMM2 (H @ w_down^T)*score -> Y --------
// BM=128, BN=128, BK=32, 3-pass bf16.
__global__ void __launch_bounds__(256, 1) k_ffn2_mma(const float* __restrict__ wd) {
    extern __shared__ __align__(16) uint16_t sm[];
    const int e = blockIdx.z;
    const int cnt = min(g_counts[e], CAP);
    const int m0 = blockIdx.y * 128;
    if (m0 >= cnt) return;
    const int n0 = blockIdx.x * 128;
    const int tid = threadIdx.x;
    const uint32_t sbase = smem_u32(sm);

    // A (H, bf16 pre-split) via cp.async
    const int arow = tid >> 1, ak = (tid & 1) * 16;
    const uint16_t* gah = (const uint16_t*)g_Hhi + ((size_t)e * CAP + m0 + arow) * FFN + ak;
    const uint16_t* gal = (const uint16_t*)g_Hlo + ((size_t)e * CAP + m0 + arow) * FFN + ak;
    const uint32_t sAoff = (uint32_t)(arow * SROW + ak) * 2;

    // B (w_down fp32): row = tid>>1 (0..127), k seg = (tid&1)*16
    const int brow = tid >> 1, bk = (tid & 1) * 16;
    const float* gb = wd + (size_t)e * DIM * FFN + (size_t)(n0 + brow) * FFN + bk;
    const uint32_t bidx = (uint32_t)(brow * SROW + bk);

    const int wid = tid >> 5, lane = tid & 31;
    const int wm = wid >> 1, wn = wid & 1;
    const int fg = lane >> 2, ft = lane & 3;

    float cd[2][8][4] = {};
    float4 rb0, rb1, rb2, rb3;

    {
        uint32_t d = sbase + sAoff;
        cpasync16(d, gah); cpasync16(d + 16, gah + 8);
        cpasync16(d + S2_AL * 2, gal); cpasync16(d + S2_AL * 2 + 16, gal + 8);
        CP_COMMIT();
        rb0 = *(const float4*)gb;       rb1 = *(const float4*)(gb + 4);
        rb2 = *(const float4*)(gb + 8); rb3 = *(const float4*)(gb + 12);
    }

    const int C = FFN / 32;
    for (int c = 0; c < C; c++) {
        const int st = c & 1;
        uint16_t* S = sm + st * STAGE_H;
        CP_WAIT0();
        {
            uint4 hi, lo;
            hilo8(rb0, rb1, hi, lo);
            *(uint4*)&S[S2_BH + bidx] = hi;
            *(uint4*)&S[S2_BL + bidx] = lo;
            hilo8(rb2, rb3, hi, lo);
            *(uint4*)&S[S2_BH + bidx + 8] = hi;
            *(uint4*)&S[S2_BL + bidx + 8] = lo;
        }
        __syncthreads();
        if (c + 1 < C) {
            const int kk = (c + 1) * 32;
            uint32_t d = sbase + (uint32_t)(st ^ 1) * STAGE_H * 2 + sAoff;
            cpasync16(d, gah + kk); cpasync16(d + 16, gah + kk + 8);
            cpasync16(d + S2_AL * 2, gal + kk); cpasync16(d + S2_AL * 2 + 16, gal + kk + 8);
            CP_COMMIT();
            rb0 = *(const float4*)(gb + kk);     rb1 = *(const float4*)(gb + kk + 4);
            rb2 = *(const float4*)(gb + kk + 8); rb3 = *(const float4*)(gb + kk + 12);
        }
        #pragma unroll
        for (int ks = 0; ks < 2; ks++) {
            const int kb = ks * 16 + ft * 2;
            uint32_t ah[2][4], al[2][4];
            #pragma unroll
            for (int i = 0; i < 2; i++) {
                const int r = wm * 32 + i * 16 + fg;
                ah[i][0] = ld32s(&S[S2_AH + r * SROW + kb]);
                ah[i][1] = ld32s(&S[S2_AH + (r + 8) * SROW + kb]);
                ah[i][2] = ld32s(&S[S2_AH + r * SROW + kb + 8]);
                ah[i][3] = ld32s(&S[S2_AH + (r + 8) * SROW + kb + 8]);
                al[i][0] = ld32s(&S[S2_AL + r * SROW + kb]);
                al[i][1] = ld32s(&S[S2_AL + (r + 8) * SROW + kb]);
                al[i][2] = ld32s(&S[S2_AL + r * SROW + kb + 8]);
                al[i][3] = ld32s(&S[S2_AL + (r + 8) * SROW + kb + 8]);
            }
            uint32_t bh[8][2], bl[8][2];
            #pragma unroll
            for (int j = 0; j < 8; j++) {
                const int cb = (wn * 64 + j * 8 + fg) * SROW + ks * 16 + ft * 2;
                bh[j][0] = ld32s(&S[S2_BH + cb]); bh[j][1] = ld32s(&S[S2_BH + cb + 8]);
                bl[j][0] = ld32s(&S[S2_BL + cb]); bl[j][1] = ld32s(&S[S2_BL + cb + 8]);
            }
            #pragma unroll
            for (int i = 0; i < 2; i++)
                #pragma unroll
                for (int j = 0; j < 8; j++) {
                    mma16816(cd[i][j], ah[i], bh[j]);
                    mma16816(cd[i][j], ah[i], bl[j]);
                    mma16816(cd[i][j], al[i], bh[j]);
                }
        }
        __syncthreads();
    }

    // epilogue: y * score -> g_Y
    const size_t ebase = (size_t)e * CAP;
    #pragma unroll
    for (int i = 0; i < 2; i++)
        #pragma unroll
        for (int j = 0; j < 8; j++) {
            const int r0 = m0 + wm * 32 + i * 16 + fg;
            const int col = n0 + wn * 64 + j * 8 + ft * 2;
            #pragma unroll
            for (int h = 0; h < 2; h++) {
                const int r = r0 + h * 8;
                const float s = g_score[ebase + r];
                float2 o;
                o.x = cd[i][j][2 * h] * s;
                o.y = cd[i][j][2 * h + 1] * s;
                *(float2*)&g_Y[(ebase + r) * DIM + col] = o;
            }
        }
}

// ---------------- kernel 5: combine ----------------
__global__ void __launch_bounds__(256) k_combine(float* __restrict__ out) {
    int t = blockIdx.x;
    int tid = threadIdx.x;
    float4 a0 = make_float4(0.f, 0.f, 0.f, 0.f);
    float4 a1 = make_float4(0.f, 0.f, 0.f, 0.f);
    #pragma unroll
    for (int k = 0; k < TOPK; k++) {
        int loc = g_loc[t * TOPK + k];
        if (loc < 0) continue;
        const float4* y = (const float4*)(g_Y + (size_t)loc * DIM);
        float4 v0 = y[tid * 2], v1 = y[tid * 2 + 1];
        a0.x += v0.x; a0.y += v0.y; a0.z += v0.z; a0.w += v0.w;
        a1.x += v1.x; a1.y += v1.y; a1.z += v1.z; a1.w += v1.w;
    }
    float4* o = (float4*)(out + (size_t)t * DIM);
    o[tid * 2] = a0;
    o[tid * 2 + 1] = a1;
}

// ---------------- launch ----------------
extern "C" void kernel_launch(void* const* d_in, const int* in_sizes, int n_in,
                              void* d_out, int out_size) {
    const float* x  = (const float*)d_in[0];   // hidden_states [1,2048,2048]
    const float* gw = (const float*)d_in[1];   // gate_w  [64,2048]
    const float* wg = (const float*)d_in[2];   // w_gate  [64,768,2048]
    const float* wu = (const float*)d_in[3];   // w_up    [64,768,2048]
    const float* wd = (const float*)d_in[4];   // w_down  [64,2048,768]
    float* out = (float*)d_out;

    cudaFuncSetAttribute(k_ffn1_mma, cudaFuncAttributeMaxDynamicSharedMemorySize, SMEM_BYTES);
    cudaFuncSetAttribute(k_ffn2_mma, cudaFuncAttributeMaxDynamicSharedMemorySize, SMEM_BYTES);

    k_zero_counts<<<1, 64>>>();
    k_xsplit<<<(NTOK * DIM) / (256 * 8), 256>>>(x);
    k_gating<<<NTOK, 128>>>(x, gw);
    k_ffn1_mma<<<dim3(FFN / 64, CAP / 128, NEXP), 256, SMEM_BYTES>>>(wg, wu);
    k_ffn2_mma<<<dim3(DIM / 128, CAP / 128, NEXP), 256, SMEM_BYTES>>>(wd);
    k_combine<<<NTOK, 256>>>(out);
}

// round 7
// speedup vs baseline: 2.2015x; 1.0223x over previous
#include <cuda_runtime.h>
#include <cuda_bf16.h>
#include <stdint.h>
#include <math.h>

#define NTOK 2048
#define DIM  2048
#define NEXP 64
#define TOPK 8
#define FFN  768
#define CAP  512

// ---------------- device scratch ----------------
__device__ int   g_counts[NEXP];
__device__ int   g_tok[NEXP * CAP];
__device__ float g_score[NEXP * CAP];
__device__ int   g_loc[NTOK * TOPK];
__device__ __align__(16) __nv_bfloat16 g_xhi[(size_t)NTOK * DIM];
__device__ __align__(16) __nv_bfloat16 g_xlo[(size_t)NTOK * DIM];
__device__ __align__(16) __nv_bfloat16 g_Hhi[(size_t)NEXP * CAP * FFN];
__device__ __align__(16) __nv_bfloat16 g_Hlo[(size_t)NEXP * CAP * FFN];
__device__ __align__(16) float g_Y[(size_t)NEXP * CAP * DIM];

// ---------------- helpers ----------------
static __device__ __forceinline__ uint32_t smem_u32(const void* p) {
    uint32_t a;
    asm("{ .reg .u64 t; cvta.to.shared.u64 t, %1; cvt.u32.u64 %0, t; }" : "=r"(a) : "l"(p));
    return a;
}
static __device__ __forceinline__ void cpasync16(uint32_t s, const void* g) {
    asm volatile("cp.async.ca.shared.global [%0], [%1], 16;" :: "r"(s), "l"(g));
}
#define CP_COMMIT() asm volatile("cp.async.commit_group;" ::: "memory")
#define CP_WAIT0()  asm volatile("cp.async.wait_group 0;" ::: "memory")

static __device__ __forceinline__ void ldsm4(uint32_t* r, uint32_t addr) {
    asm volatile("ldmatrix.sync.aligned.m8n8.x4.shared.b16 {%0,%1,%2,%3}, [%4];"
        : "=r"(r[0]), "=r"(r[1]), "=r"(r[2]), "=r"(r[3]) : "r"(addr));
}

static __device__ __forceinline__ void mma16816(float* c, const uint32_t* a, const uint32_t* b) {
    asm volatile("mma.sync.aligned.m16n8k16.row.col.f32.bf16.bf16.f32 "
        "{%0,%1,%2,%3}, {%4,%5,%6,%7}, {%8,%9}, {%0,%1,%2,%3};"
        : "+f"(c[0]), "+f"(c[1]), "+f"(c[2]), "+f"(c[3])
        : "r"(a[0]), "r"(a[1]), "r"(a[2]), "r"(a[3]), "r"(b[0]), "r"(b[1]));
}

// fp32 -> bf16 hi + bf16 lo (pairwise packed in b32)
static __device__ __forceinline__ void cvt2(float a0, float a1, uint32_t& hi2, uint32_t& lo2) {
    asm("cvt.rn.bf16x2.f32 %0, %1, %2;" : "=r"(hi2) : "f"(a1), "f"(a0));
    float h0 = __uint_as_float(hi2 << 16);
    float h1 = __uint_as_float(hi2 & 0xffff0000u);
    float l0 = a0 - h0, l1 = a1 - h1;
    asm("cvt.rn.bf16x2.f32 %0, %1, %2;" : "=r"(lo2) : "f"(l1), "f"(l0));
}
static __device__ __forceinline__ void hilo8(float4 a, float4 b, uint4& hi, uint4& lo) {
    cvt2(a.x, a.y, hi.x, lo.x);
    cvt2(a.z, a.w, hi.y, lo.y);
    cvt2(b.x, b.y, hi.z, lo.z);
    cvt2(b.z, b.w, hi.w, lo.w);
}

// ---------------- kernel 0: zero counters ----------------
__global__ void k_zero_counts() {
    if (threadIdx.x < NEXP) g_counts[threadIdx.x] = 0;
}

// ---------------- kernel 1: split x into bf16 hi/lo ----------------
__global__ void __launch_bounds__(256) k_xsplit(const float* __restrict__ x) {
    size_t base = ((size_t)blockIdx.x * 256 + threadIdx.x) * 8;
    float4 a = *(const float4*)(x + base);
    float4 b = *(const float4*)(x + base + 4);
    uint4 hi, lo;
    hilo8(a, b, hi, lo);
    *(uint4*)((uint16_t*)g_xhi + base) = hi;
    *(uint4*)((uint16_t*)g_xlo + base) = lo;
}

// ---------------- kernel 2: gating ----------------
__global__ void __launch_bounds__(128) k_gating(const float* __restrict__ x,
                                                const float* __restrict__ gw) {
    int t = blockIdx.x;
    __shared__ float4 xs4[DIM / 4];
    __shared__ float prob[NEXP];

    int tid = threadIdx.x, lane = tid & 31, warp = tid >> 5;
    const float4* xg = (const float4*)(x + (size_t)t * DIM);
    for (int i = tid; i < DIM / 4; i += 128) xs4[i] = xg[i];
    __syncthreads();

    for (int e = 0; e < 16; e++) {
        int ex = warp * 16 + e;
        const float4* g4 = (const float4*)(gw + (size_t)ex * DIM);
        float s = 0.f;
        for (int j = lane; j < DIM / 4; j += 32) {
            float4 a = g4[j];
            float4 b = xs4[j];
            s += a.x * b.x + a.y * b.y + a.z * b.z + a.w * b.w;
        }
        #pragma unroll
        for (int o = 16; o > 0; o >>= 1) s += __shfl_down_sync(0xffffffffu, s, o);
        if (lane == 0) prob[ex] = s;
    }
    __syncthreads();

    if (warp == 0) {
        float l0 = prob[lane], l1 = prob[lane + 32];
        float m = fmaxf(l0, l1);
        #pragma unroll
        for (int o = 16; o > 0; o >>= 1) m = fmaxf(m, __shfl_xor_sync(0xffffffffu, m, o));
        float p0 = expf(l0 - m), p1 = expf(l1 - m);
        float z = p0 + p1;
        #pragma unroll
        for (int o = 16; o > 0; o >>= 1) z += __shfl_xor_sync(0xffffffffu, z, o);
        float inv = 1.f / z;
        prob[lane] = p0 * inv;
        prob[lane + 32] = p1 * inv;
        __syncwarp();

        for (int k = 0; k < TOPK; k++) {
            float v0 = prob[lane], v1 = prob[lane + 32];
            float bv = v0; int bi = lane;
            if (v1 > v0) { bv = v1; bi = lane + 32; }
            #pragma unroll
            for (int o = 16; o > 0; o >>= 1) {
                float ov = __shfl_down_sync(0xffffffffu, bv, o);
                int   oi = __shfl_down_sync(0xffffffffu, bi, o);
                if (ov > bv || (ov == bv && oi < bi)) { bv = ov; bi = oi; }
            }
            if (lane == 0) {
                int e = bi;
                float s = prob[bi];
                int slot = atomicAdd(&g_counts[e], 1);
                int loc = -1;
                if (slot < CAP) {
                    loc = e * CAP + slot;
                    g_tok[loc] = t;
                    g_score[loc] = s;
                }
                g_loc[t * TOPK + k] = loc;
                prob[bi] = -1.f;
            }
            __syncwarp();
        }
    }
}

// ====================== GEMM smem layout (halves) ======================
#define SROW 40
#define STAGE_H 20480
#define SMEM_BYTES (2 * STAGE_H * 2)

#define S1_AH 0
#define S1_AL 5120
#define S1_GH 10240
#define S1_GL 12800
#define S1_UH 15360
#define S1_UL 17920

#define S2_AH 0
#define S2_AL 5120
#define S2_BH 10240
#define S2_BL 15360

// ---- FFN1: one ks-step of fragment loads + 24 MMAs ----
static __device__ __forceinline__ void ffn1_step(uint32_t Sb, int ks, int wm, int wn, int lane,
                                                 float cg[2][4][4], float cu[2][4][4]) {
    const int arow_f = wm * 32 + (lane & 15);
    const int kofA = ks * 16 + ((lane >> 4) << 3);
    uint32_t ah[2][4], al[2][4];
    #pragma unroll
    for (int i = 0; i < 2; i++) {
        uint32_t ad = Sb + (uint32_t)((S1_AH + (arow_f + i * 16) * SROW + kofA) * 2);
        ldsm4(ah[i], ad);
        ldsm4(al[i], ad + (S1_AL - S1_AH) * 2);
    }
    const int g = lane >> 3;
    const int jrow = ((g >> 1) << 3) + (lane & 7);
    const int kofB = ks * 16 + ((g & 1) << 3);
    uint32_t bgh[4][2], bgl[4][2], buh[4][2], bul[4][2];
    #pragma unroll
    for (int j2 = 0; j2 < 2; j2++) {
        uint32_t nrow = (uint32_t)(wn * 32 + j2 * 16 + jrow);
        uint32_t bd = Sb + (uint32_t)((S1_GH + nrow * SROW + kofB) * 2);
        ldsm4(&bgh[2 * j2][0], bd);
        ldsm4(&bgl[2 * j2][0], bd + (S1_GL - S1_GH) * 2);
        ldsm4(&buh[2 * j2][0], bd + (S1_UH - S1_GH) * 2);
        ldsm4(&bul[2 * j2][0], bd + (S1_UL - S1_GH) * 2);
    }
    #pragma unroll
    for (int i = 0; i < 2; i++)
        #pragma unroll
        for (int j = 0; j < 4; j++) {
            mma16816(cg[i][j], ah[i], bgh[j]);
            mma16816(cg[i][j], ah[i], bgl[j]);
            mma16816(cg[i][j], al[i], bgh[j]);
            mma16816(cu[i][j], ah[i], buh[j]);
            mma16816(cu[i][j], ah[i], bul[j]);
            mma16816(cu[i][j], al[i], buh[j]);
        }
}

// ---------------- kernel 3: grouped GEMM1 (gate+up) + SwiGLU -> Hhi/Hlo ----
__global__ void __launch_bounds__(256, 1) k_ffn1_mma(const float* __restrict__ wg,
                                                     const float* __restrict__ wu) {
    extern __shared__ __align__(16) uint16_t sm[];
    const int e = blockIdx.z;
    const int cnt = min(g_counts[e], CAP);
    const int m0 = blockIdx.y * 128;
    if (m0 >= cnt) return;
    const int n0 = blockIdx.x * 64;
    const int tid = threadIdx.x;
    const uint32_t sbase = smem_u32(sm);

    const int arow = tid >> 1, ak = (tid & 1) * 16;
    const int tr = m0 + arow;
    const int tok = (tr < cnt) ? g_tok[e * CAP + tr] : 0;
    const uint16_t* gah = (const uint16_t*)g_xhi + (size_t)tok * DIM + ak;
    const uint16_t* gal = (const uint16_t*)g_xlo + (size_t)tok * DIM + ak;
    const uint32_t sAoff = (uint32_t)(arow * SROW + ak) * 2;

    const int brow = tid >> 2, bk = (tid & 3) * 8;
    const float* gbg = wg + (size_t)e * FFN * DIM + (size_t)(n0 + brow) * DIM + bk;
    const float* gbu = wu + (size_t)e * FFN * DIM + (size_t)(n0 + brow) * DIM + bk;
    const uint32_t bidx = (uint32_t)(brow * SROW + bk);

    const int wid = tid >> 5, lane = tid & 31;
    const int wm = wid >> 1, wn = wid & 1;
    const int fg = lane >> 2, ft = lane & 3;

    float cg[2][4][4] = {};
    float cu[2][4][4] = {};
    float4 rg0, rg1, ru0, ru1;

    // prologue: A0 via cp.async, B0 load+convert+store into stage 0
    {
        uint32_t d = sbase + sAoff;
        cpasync16(d, gah); cpasync16(d + 16, gah + 8);
        cpasync16(d + S1_AL * 2, gal); cpasync16(d + S1_AL * 2 + 16, gal + 8);
        CP_COMMIT();
        rg0 = *(const float4*)gbg; rg1 = *(const float4*)(gbg + 4);
        ru0 = *(const float4*)gbu; ru1 = *(const float4*)(gbu + 4);
        uint4 hi, lo;
        hilo8(rg0, rg1, hi, lo);
        *(uint4*)&sm[S1_GH + bidx] = hi;
        *(uint4*)&sm[S1_GL + bidx] = lo;
        hilo8(ru0, ru1, hi, lo);
        *(uint4*)&sm[S1_UH + bidx] = hi;
        *(uint4*)&sm[S1_UL + bidx] = lo;
    }

    const int C = DIM / 32;
    for (int c = 0; c < C; c++) {
        const int st = c & 1;
        const uint32_t Sb = sbase + (uint32_t)st * (STAGE_H * 2);
        CP_WAIT0();
        __syncthreads();
        const bool more = (c + 1 < C);
        if (more) {
            const int kk = (c + 1) * 32;
            uint32_t d = sbase + (uint32_t)(st ^ 1) * (STAGE_H * 2) + sAoff;
            cpasync16(d, gah + kk); cpasync16(d + 16, gah + kk + 8);
            cpasync16(d + S1_AL * 2, gal + kk); cpasync16(d + S1_AL * 2 + 16, gal + kk + 8);
            CP_COMMIT();
            rg0 = *(const float4*)(gbg + kk); rg1 = *(const float4*)(gbg + kk + 4);
            ru0 = *(const float4*)(gbu + kk); ru1 = *(const float4*)(gbu + kk + 4);
        }
        ffn1_step(Sb, 0, wm, wn, lane, cg, cu);
        if (more) {
            uint16_t* Sn = sm + (st ^ 1) * STAGE_H;
            uint4 hi, lo;
            hilo8(rg0, rg1, hi, lo);
            *(uint4*)&Sn[S1_GH + bidx] = hi;
            *(uint4*)&Sn[S1_GL + bidx] = lo;
            hilo8(ru0, ru1, hi, lo);
            *(uint4*)&Sn[S1_UH + bidx] = hi;
            *(uint4*)&Sn[S1_UL + bidx] = lo;
        }
        ffn1_step(Sb, 1, wm, wn, lane, cg, cu);
    }

    // epilogue: h = silu(g)*u -> bf16 hi/lo
    uint16_t* hh = (uint16_t*)g_Hhi;
    uint16_t* hl = (uint16_t*)g_Hlo;
    const size_t ebase = (size_t)e * CAP;
    #pragma unroll
    for (int i = 0; i < 2; i++)
        #pragma unroll
        for (int j = 0; j < 4; j++) {
            const int r0 = m0 + wm * 32 + i * 16 + fg;
            const int col = n0 + wn * 32 + j * 8 + ft * 2;
            #pragma unroll
            for (int h = 0; h < 2; h++) {
                const int r = r0 + h * 8;
                float gv0 = cg[i][j][2 * h], gv1 = cg[i][j][2 * h + 1];
                float uv0 = cu[i][j][2 * h], uv1 = cu[i][j][2 * h + 1];
                float h0 = gv0 / (1.f + __expf(-gv0)) * uv0;
                float h1 = gv1 / (1.f + __expf(-gv1)) * uv1;
                uint32_t hi, lo;
                cvt2(h0, h1, hi, lo);
                *(uint32_t*)&hh[(ebase + r) * FFN + col] = hi;
                *(uint32_t*)&hl[(ebase + r) * FFN + col] = lo;
            }
        }
}

// ---- FFN2: one ks-step of fragment loads + 24 MMAs ----
static __device__ __forceinline__ void ffn2_step(uint32_t Sb, int ks, int wm, int wn, int lane,
                                                 float cd[2][8][4]) {
    const int arow_f = wm * 32 + (lane & 15);
    const int kofA = ks * 16 + ((lane >> 4) << 3);
    uint32_t ah[2][4], al[2][4];
    #pragma unroll
    for (int i = 0; i < 2; i++) {
        uint32_t ad = Sb + (uint32_t)((S2_AH + (arow_f + i * 16) * SROW + kofA) * 2);
        ldsm4(ah[i], ad);
        ldsm4(al[i], ad + (S2_AL - S2_AH) * 2);
    }
    const int g = lane >> 3;
    const int jrow = ((g >> 1) << 3) + (lane & 7);
    const int kofB = ks * 16 + ((g & 1) << 3);
    uint32_t bh[8][2], bl[8][2];
    #pragma unroll
    for (int j2 = 0; j2 < 4; j2++) {
        uint32_t nrow = (uint32_t)(wn * 64 + j2 * 16 + jrow);
        uint32_t bd = Sb + (uint32_t)((S2_BH + nrow * SROW + kofB) * 2);
        ldsm4(&bh[2 * j2][0], bd);
        ldsm4(&bl[2 * j2][0], bd + (S2_BL - S2_BH) * 2);
    }
    #pragma unroll
    for (int i = 0; i < 2; i++)
        #pragma unroll
        for (int j = 0; j < 8; j++) {
            mma16816(cd[i][j], ah[i], bh[j]);
            mma16816(cd[i][j], ah[i], bl[j]);
            mma16816(cd[i][j], al[i], bh[j]);
        }
}

// ---------------- kernel 4: grouped GEMM2 (H @ w_down^T)*score -> Y --------
__global__ void __launch_bounds__(256, 1) k_ffn2_mma(const float* __restrict__ wd) {
    extern __shared__ __align__(16) uint16_t sm[];
    const int e = blockIdx.z;
    const int cnt = min(g_counts[e], CAP);
    const int m0 = blockIdx.y * 128;
    if (m0 >= cnt) return;
    const int n0 = blockIdx.x * 128;
    const int tid = threadIdx.x;
    const uint32_t sbase = smem_u32(sm);

    const int arow = tid >> 1, ak = (tid & 1) * 16;
    const uint16_t* gah = (const uint16_t*)g_Hhi + ((size_t)e * CAP + m0 + arow) * FFN + ak;
    const uint16_t* gal = (const uint16_t*)g_Hlo + ((size_t)e * CAP + m0 + arow) * FFN + ak;
    const uint32_t sAoff = (uint32_t)(arow * SROW + ak) * 2;

    const int brow = tid >> 1, bk = (tid & 1) * 16;
    const float* gb = wd + (size_t)e * DIM * FFN + (size_t)(n0 + brow) * FFN + bk;
    const uint32_t bidx = (uint32_t)(brow * SROW + bk);

    const int wid = tid >> 5, lane = tid & 31;
    const int wm = wid >> 1, wn = wid & 1;
    const int fg = lane >> 2, ft = lane & 3;

    float cd[2][8][4] = {};
    float4 rb0, rb1, rb2, rb3;

    {
        uint32_t d = sbase + sAoff;
        cpasync16(d, gah); cpasync16(d + 16, gah + 8);
        cpasync16(d + S2_AL * 2, gal); cpasync16(d + S2_AL * 2 + 16, gal + 8);
        CP_COMMIT();
        rb0 = *(const float4*)gb;       rb1 = *(const float4*)(gb + 4);
        rb2 = *(const float4*)(gb + 8); rb3 = *(const float4*)(gb + 12);
        uint4 hi, lo;
        hilo8(rb0, rb1, hi, lo);
        *(uint4*)&sm[S2_BH + bidx] = hi;
        *(uint4*)&sm[S2_BL + bidx] = lo;
        hilo8(rb2, rb3, hi, lo);
        *(uint4*)&sm[S2_BH + bidx + 8] = hi;
        *(uint4*)&sm[S2_BL + bidx + 8] = lo;
    }

    const int C = FFN / 32;
    for (int c = 0; c < C; c++) {
        const int st = c & 1;
        const uint32_t Sb = sbase + (uint32_t)st * (STAGE_H * 2);
        CP_WAIT0();
        __syncthreads();
        const bool more = (c + 1 < C);
        if (more) {
            const int kk = (c + 1) * 32;
            uint32_t d = sbase + (uint32_t)(st ^ 1) * (STAGE_H * 2) + sAoff;
            cpasync16(d, gah + kk); cpasync16(d + 16, gah + kk + 8);
            cpasync16(d + S2_AL * 2, gal + kk); cpasync16(d + S2_AL * 2 + 16, gal + kk + 8);
            CP_COMMIT();
            rb0 = *(const float4*)(gb + kk);     rb1 = *(const float4*)(gb + kk + 4);
            rb2 = *(const float4*)(gb + kk + 8); rb3 = *(const float4*)(gb + kk + 12);
        }
        ffn2_step(Sb, 0, wm, wn, lane, cd);
        if (more) {
            uint16_t* Sn = sm + (st ^ 1) * STAGE_H;
            uint4 hi, lo;
            hilo8(rb0, rb1, hi, lo);
            *(uint4*)&Sn[S2_BH + bidx] = hi;
            *(uint4*)&Sn[S2_BL + bidx] = lo;
            hilo8(rb2, rb3, hi, lo);
            *(uint4*)&Sn[S2_BH + bidx + 8] = hi;
            *(uint4*)&Sn[S2_BL + bidx + 8] = lo;
        }
        ffn2_step(Sb, 1, wm, wn, lane, cd);
    }

    // epilogue: y * score -> g_Y
    const size_t ebase = (size_t)e * CAP;
    #pragma unroll
    for (int i = 0; i < 2; i++)
        #pragma unroll
        for (int j = 0; j < 8; j++) {
            const int r0 = m0 + wm * 32 + i * 16 + fg;
            const int col = n0 + wn * 64 + j * 8 + ft * 2;
            #pragma unroll
            for (int h = 0; h < 2; h++) {
                const int r = r0 + h * 8;
                const float s = g_score[ebase + r];
                float2 o;
                o.x = cd[i][j][2 * h] * s;
                o.y = cd[i][j][2 * h + 1] * s;
                *(float2*)&g_Y[(ebase + r) * DIM + col] = o;
            }
        }
}

// ---------------- kernel 5: combine ----------------
__global__ void __launch_bounds__(256) k_combine(float* __restrict__ out) {
    int t = blockIdx.x;
    int tid = threadIdx.x;
    float4 a0 = make_float4(0.f, 0.f, 0.f, 0.f);
    float4 a1 = make_float4(0.f, 0.f, 0.f, 0.f);
    #pragma unroll
    for (int k = 0; k < TOPK; k++) {
        int loc = g_loc[t * TOPK + k];
        if (loc < 0) continue;
        const float4* y = (const float4*)(g_Y + (size_t)loc * DIM);
        float4 v0 = y[tid * 2], v1 = y[tid * 2 + 1];
        a0.x += v0.x; a0.y += v0.y; a0.z += v0.z; a0.w += v0.w;
        a1.x += v1.x; a1.y += v1.y; a1.z += v1.z; a1.w += v1.w;
    }
    float4* o = (float4*)(out + (size_t)t * DIM);
    o[tid * 2] = a0;
    o[tid * 2 + 1] = a1;
}

// ---------------- launch ----------------
extern "C" void kernel_launch(void* const* d_in, const int* in_sizes, int n_in,
                              void* d_out, int out_size) {
    const float* x  = (const float*)d_in[0];   // hidden_states [1,2048,2048]
    const float* gw = (const float*)d_in[1];   // gate_w  [64,2048]
    const float* wg = (const float*)d_in[2];   // w_gate  [64,768,2048]
    const float* wu = (const float*)d_in[3];   // w_up    [64,768,2048]
    const float* wd = (const float*)d_in[4];   // w_down  [64,2048,768]
    float* out = (float*)d_out;

    cudaFuncSetAttribute(k_ffn1_mma, cudaFuncAttributeMaxDynamicSharedMemorySize, SMEM_BYTES);
    cudaFuncSetAttribute(k_ffn2_mma, cudaFuncAttributeMaxDynamicSharedMemorySize, SMEM_BYTES);

    k_zero_counts<<<1, 64>>>();
    k_xsplit<<<(NTOK * DIM) / (256 * 8), 256>>>(x);
    k_gating<<<NTOK, 128>>>(x, gw);
    k_ffn1_mma<<<dim3(FFN / 64, CAP / 128, NEXP), 256, SMEM_BYTES>>>(wg, wu);
    k_ffn2_mma<<<dim3(DIM / 128, CAP / 128, NEXP), 256, SMEM_BYTES>>>(wd);
    k_combine<<<NTOK, 256>>>(out);
}

// round 8
// speedup vs baseline: 2.5385x; 1.1531x over previous
#include <cuda_runtime.h>
#include <cuda_bf16.h>
#include <stdint.h>
#include <math.h>

#define NTOK 2048
#define DIM  2048
#define NEXP 64
#define TOPK 8
#define FFN  768
#define CAP  512

// ---------------- device scratch ----------------
__device__ int   g_counts[NEXP];
__device__ int   g_tok[NEXP * CAP];
__device__ float g_score[NEXP * CAP];
__device__ int   g_loc[NTOK * TOPK];
__device__ __align__(16) __nv_bfloat16 g_xhi[(size_t)NTOK * DIM];
__device__ __align__(16) __nv_bfloat16 g_xlo[(size_t)NTOK * DIM];
__device__ __align__(16) __nv_bfloat16 g_Hhi[(size_t)NEXP * CAP * FFN];
__device__ __align__(16) __nv_bfloat16 g_Hlo[(size_t)NEXP * CAP * FFN];
__device__ __align__(16) float g_Y[(size_t)NEXP * CAP * DIM];

// ---------------- helpers ----------------
static __device__ __forceinline__ uint32_t smem_u32(const void* p) {
    uint32_t a;
    asm("{ .reg .u64 t; cvta.to.shared.u64 t, %1; cvt.u32.u64 %0, t; }" : "=r"(a) : "l"(p));
    return a;
}
static __device__ __forceinline__ void cpasync16(uint32_t s, const void* g) {
    asm volatile("cp.async.ca.shared.global [%0], [%1], 16;" :: "r"(s), "l"(g));
}
#define CP_COMMIT() asm volatile("cp.async.commit_group;" ::: "memory")
#define CP_WAIT0()  asm volatile("cp.async.wait_group 0;" ::: "memory")

static __device__ __forceinline__ void ldsm4(uint32_t* r, uint32_t addr) {
    asm volatile("ldmatrix.sync.aligned.m8n8.x4.shared.b16 {%0,%1,%2,%3}, [%4];"
        : "=r"(r[0]), "=r"(r[1]), "=r"(r[2]), "=r"(r[3]) : "r"(addr));
}

static __device__ __forceinline__ void mma16816(float* c, const uint32_t* a, const uint32_t* b) {
    asm volatile("mma.sync.aligned.m16n8k16.row.col.f32.bf16.bf16.f32 "
        "{%0,%1,%2,%3}, {%4,%5,%6,%7}, {%8,%9}, {%0,%1,%2,%3};"
        : "+f"(c[0]), "+f"(c[1]), "+f"(c[2]), "+f"(c[3])
        : "r"(a[0]), "r"(a[1]), "r"(a[2]), "r"(a[3]), "r"(b[0]), "r"(b[1]));
}

// fp32 -> bf16 hi + bf16 lo (pairwise packed in b32)
static __device__ __forceinline__ void cvt2(float a0, float a1, uint32_t& hi2, uint32_t& lo2) {
    asm("cvt.rn.bf16x2.f32 %0, %1, %2;" : "=r"(hi2) : "f"(a1), "f"(a0));
    float h0 = __uint_as_float(hi2 << 16);
    float h1 = __uint_as_float(hi2 & 0xffff0000u);
    float l0 = a0 - h0, l1 = a1 - h1;
    asm("cvt.rn.bf16x2.f32 %0, %1, %2;" : "=r"(lo2) : "f"(l1), "f"(l0));
}
static __device__ __forceinline__ void hilo8(float4 a, float4 b, uint4& hi, uint4& lo) {
    cvt2(a.x, a.y, hi.x, lo.x);
    cvt2(a.z, a.w, hi.y, lo.y);
    cvt2(b.x, b.y, hi.z, lo.z);
    cvt2(b.z, b.w, hi.w, lo.w);
}

// ---------------- kernel 0: zero counters ----------------
__global__ void k_zero_counts() {
    if (threadIdx.x < NEXP) g_counts[threadIdx.x] = 0;
}

// ---------------- kernel 1: split x into bf16 hi/lo ----------------
__global__ void __launch_bounds__(256) k_xsplit(const float* __restrict__ x) {
    size_t base = ((size_t)blockIdx.x * 256 + threadIdx.x) * 8;
    float4 a = *(const float4*)(x + base);
    float4 b = *(const float4*)(x + base + 4);
    uint4 hi, lo;
    hilo8(a, b, hi, lo);
    *(uint4*)((uint16_t*)g_xhi + base) = hi;
    *(uint4*)((uint16_t*)g_xlo + base) = lo;
}

// ---------------- kernel 2: gating ----------------
__global__ void __launch_bounds__(128) k_gating(const float* __restrict__ x,
                                                const float* __restrict__ gw) {
    int t = blockIdx.x;
    __shared__ float4 xs4[DIM / 4];
    __shared__ float prob[NEXP];

    int tid = threadIdx.x, lane = tid & 31, warp = tid >> 5;
    const float4* xg = (const float4*)(x + (size_t)t * DIM);
    for (int i = tid; i < DIM / 4; i += 128) xs4[i] = xg[i];
    __syncthreads();

    for (int e = 0; e < 16; e++) {
        int ex = warp * 16 + e;
        const float4* g4 = (const float4*)(gw + (size_t)ex * DIM);
        float s = 0.f;
        for (int j = lane; j < DIM / 4; j += 32) {
            float4 a = g4[j];
            float4 b = xs4[j];
            s += a.x * b.x + a.y * b.y + a.z * b.z + a.w * b.w;
        }
        #pragma unroll
        for (int o = 16; o > 0; o >>= 1) s += __shfl_down_sync(0xffffffffu, s, o);
        if (lane == 0) prob[ex] = s;
    }
    __syncthreads();

    if (warp == 0) {
        float l0 = prob[lane], l1 = prob[lane + 32];
        float m = fmaxf(l0, l1);
        #pragma unroll
        for (int o = 16; o > 0; o >>= 1) m = fmaxf(m, __shfl_xor_sync(0xffffffffu, m, o));
        float p0 = expf(l0 - m), p1 = expf(l1 - m);
        float z = p0 + p1;
        #pragma unroll
        for (int o = 16; o > 0; o >>= 1) z += __shfl_xor_sync(0xffffffffu, z, o);
        float inv = 1.f / z;
        prob[lane] = p0 * inv;
        prob[lane + 32] = p1 * inv;
        __syncwarp();

        for (int k = 0; k < TOPK; k++) {
            float v0 = prob[lane], v1 = prob[lane + 32];
            float bv = v0; int bi = lane;
            if (v1 > v0) { bv = v1; bi = lane + 32; }
            #pragma unroll
            for (int o = 16; o > 0; o >>= 1) {
                float ov = __shfl_down_sync(0xffffffffu, bv, o);
                int   oi = __shfl_down_sync(0xffffffffu, bi, o);
                if (ov > bv || (ov == bv && oi < bi)) { bv = ov; bi = oi; }
            }
            if (lane == 0) {
                int e = bi;
                float s = prob[bi];
                int slot = atomicAdd(&g_counts[e], 1);
                int loc = -1;
                if (slot < CAP) {
                    loc = e * CAP + slot;
                    g_tok[loc] = t;
                    g_score[loc] = s;
                }
                g_loc[t * TOPK + k] = loc;
                prob[bi] = -1.f;
            }
            __syncwarp();
        }
    }
}

// ====================== GEMM smem layout (halves) ======================
#define SROW 40
#define STAGE_H 30720
#define SMEM_BYTES (2 * STAGE_H * 2)   // 122880 B

// FFN1 regions (halves): A 128 rows, Bg 128 cols, Bu 128 cols
#define S1_AH 0
#define S1_AL 5120
#define S1_GH 10240
#define S1_GL 15360
#define S1_UH 20480
#define S1_UL 25600

// FFN2 regions: A 128 rows, B 256 cols
#define S2_AH 0
#define S2_AL 5120
#define S2_BH 10240
#define S2_BL 20480

// ---- FFN1 step: warp tile 64m x 32n (g AND u), 96 MMAs, 16 ldsm.x4 ----
static __device__ __forceinline__ void ffn1_step(uint32_t Sb, int ks, int wm, int wn, int lane,
                                                 float cg[4][4][4], float cu[4][4][4]) {
    const int g = lane >> 3;
    const int jrow = ((g >> 1) << 3) + (lane & 7);
    const int kofB = ks * 16 + ((g & 1) << 3);
    uint32_t bgh[4][2], bgl[4][2], buh[4][2], bul[4][2];
    #pragma unroll
    for (int j2 = 0; j2 < 2; j2++) {
        uint32_t nrow = (uint32_t)(wn * 32 + j2 * 16 + jrow);
        uint32_t bd = Sb + (uint32_t)((S1_GH + nrow * SROW + kofB) * 2);
        ldsm4(&bgh[2 * j2][0], bd);
        ldsm4(&bgl[2 * j2][0], bd + (S1_GL - S1_GH) * 2);
        ldsm4(&buh[2 * j2][0], bd + (S1_UH - S1_GH) * 2);
        ldsm4(&bul[2 * j2][0], bd + (S1_UL - S1_GH) * 2);
    }
    const int kofA = ks * 16 + ((lane >> 4) << 3);
    const int arow_b = wm * 64 + (lane & 15);
    #pragma unroll
    for (int i = 0; i < 4; i++) {
        uint32_t ah[4], al[4];
        uint32_t ad = Sb + (uint32_t)((S1_AH + (arow_b + i * 16) * SROW + kofA) * 2);
        ldsm4(ah, ad);
        ldsm4(al, ad + (S1_AL - S1_AH) * 2);
        #pragma unroll
        for (int j = 0; j < 4; j++) {
            mma16816(cg[i][j], ah, bgh[j]);
            mma16816(cg[i][j], ah, bgl[j]);
            mma16816(cg[i][j], al, bgh[j]);
            mma16816(cu[i][j], ah, buh[j]);
            mma16816(cu[i][j], ah, bul[j]);
            mma16816(cu[i][j], al, buh[j]);
        }
    }
}

// ---------------- kernel 3: grouped GEMM1 (gate+up) + SwiGLU -> Hhi/Hlo ----
// CTA tile: 128 rows x 128 ffn-cols (both g and u). Warps 2m x 4n (64x32).
__global__ void __launch_bounds__(256, 1) k_ffn1_mma(const float* __restrict__ wg,
                                                     const float* __restrict__ wu) {
    extern __shared__ __align__(16) uint16_t sm[];
    const int e = blockIdx.z;
    const int cnt = min(g_counts[e], CAP);
    const int m0 = blockIdx.y * 128;
    if (m0 >= cnt) return;
    const int n0 = blockIdx.x * 128;
    const int tid = threadIdx.x;
    const uint32_t sbase = smem_u32(sm);

    // A loader: row = tid>>1, 16-half seg = tid&1
    const int arow = tid >> 1, ak = (tid & 1) * 16;
    const int tr = m0 + arow;
    const int tok = (tr < cnt) ? g_tok[e * CAP + tr] : 0;
    const uint16_t* gah = (const uint16_t*)g_xhi + (size_t)tok * DIM + ak;
    const uint16_t* gal = (const uint16_t*)g_xlo + (size_t)tok * DIM + ak;
    const uint32_t sAoff = (uint32_t)(arow * SROW + ak) * 2;

    // B loader: col-row = tid>>1 (0..127), k half = (tid&1)*16 (16 floats each of g,u)
    const int brow = tid >> 1, bk = (tid & 1) * 16;
    const float* gbg = wg + (size_t)e * FFN * DIM + (size_t)(n0 + brow) * DIM + bk;
    const float* gbu = wu + (size_t)e * FFN * DIM + (size_t)(n0 + brow) * DIM + bk;
    const uint32_t bidx = (uint32_t)(brow * SROW + bk);

    const int wid = tid >> 5, lane = tid & 31;
    const int wm = wid >> 2, wn = wid & 3;
    const int fg = lane >> 2, ft = lane & 3;

    float cg[4][4][4] = {};
    float cu[4][4][4] = {};
    float4 rg[4], ru[4];

    // prologue: A0 via cp.async, B0 load+convert+store into stage 0
    {
        uint32_t d = sbase + sAoff;
        cpasync16(d, gah); cpasync16(d + 16, gah + 8);
        cpasync16(d + S1_AL * 2, gal); cpasync16(d + S1_AL * 2 + 16, gal + 8);
        CP_COMMIT();
        #pragma unroll
        for (int q = 0; q < 4; q++) { rg[q] = *(const float4*)(gbg + 4 * q); ru[q] = *(const float4*)(gbu + 4 * q); }
        uint4 hi, lo;
        hilo8(rg[0], rg[1], hi, lo);
        *(uint4*)&sm[S1_GH + bidx] = hi; *(uint4*)&sm[S1_GL + bidx] = lo;
        hilo8(rg[2], rg[3], hi, lo);
        *(uint4*)&sm[S1_GH + bidx + 8] = hi; *(uint4*)&sm[S1_GL + bidx + 8] = lo;
        hilo8(ru[0], ru[1], hi, lo);
        *(uint4*)&sm[S1_UH + bidx] = hi; *(uint4*)&sm[S1_UL + bidx] = lo;
        hilo8(ru[2], ru[3], hi, lo);
        *(uint4*)&sm[S1_UH + bidx + 8] = hi; *(uint4*)&sm[S1_UL + bidx + 8] = lo;
    }

    const int C = DIM / 32;
    for (int c = 0; c < C; c++) {
        const int st = c & 1;
        const uint32_t Sb = sbase + (uint32_t)st * (STAGE_H * 2);
        CP_WAIT0();
        __syncthreads();
        const bool more = (c + 1 < C);
        if (more) {
            const int kk = (c + 1) * 32;
            uint32_t d = sbase + (uint32_t)(st ^ 1) * (STAGE_H * 2) + sAoff;
            cpasync16(d, gah + kk); cpasync16(d + 16, gah + kk + 8);
            cpasync16(d + S1_AL * 2, gal + kk); cpasync16(d + S1_AL * 2 + 16, gal + kk + 8);
            CP_COMMIT();
            #pragma unroll
            for (int q = 0; q < 4; q++) { rg[q] = *(const float4*)(gbg + kk + 4 * q); ru[q] = *(const float4*)(gbu + kk + 4 * q); }
        }
        ffn1_step(Sb, 0, wm, wn, lane, cg, cu);
        if (more) {
            uint16_t* Sn = sm + (st ^ 1) * STAGE_H;
            uint4 hi, lo;
            hilo8(rg[0], rg[1], hi, lo);
            *(uint4*)&Sn[S1_GH + bidx] = hi; *(uint4*)&Sn[S1_GL + bidx] = lo;
            hilo8(rg[2], rg[3], hi, lo);
            *(uint4*)&Sn[S1_GH + bidx + 8] = hi; *(uint4*)&Sn[S1_GL + bidx + 8] = lo;
            hilo8(ru[0], ru[1], hi, lo);
            *(uint4*)&Sn[S1_UH + bidx] = hi; *(uint4*)&Sn[S1_UL + bidx] = lo;
            hilo8(ru[2], ru[3], hi, lo);
            *(uint4*)&Sn[S1_UH + bidx + 8] = hi; *(uint4*)&Sn[S1_UL + bidx + 8] = lo;
        }
        ffn1_step(Sb, 1, wm, wn, lane, cg, cu);
    }

    // epilogue: h = silu(g)*u -> bf16 hi/lo
    uint16_t* hh = (uint16_t*)g_Hhi;
    uint16_t* hl = (uint16_t*)g_Hlo;
    const size_t ebase = (size_t)e * CAP;
    #pragma unroll
    for (int i = 0; i < 4; i++)
        #pragma unroll
        for (int j = 0; j < 4; j++) {
            const int r0 = m0 + wm * 64 + i * 16 + fg;
            const int col = n0 + wn * 32 + j * 8 + ft * 2;
            #pragma unroll
            for (int h = 0; h < 2; h++) {
                const int r = r0 + h * 8;
                float gv0 = cg[i][j][2 * h], gv1 = cg[i][j][2 * h + 1];
                float uv0 = cu[i][j][2 * h], uv1 = cu[i][j][2 * h + 1];
                float h0 = gv0 / (1.f + __expf(-gv0)) * uv0;
                float h1 = gv1 / (1.f + __expf(-gv1)) * uv1;
                uint32_t hi, lo;
                cvt2(h0, h1, hi, lo);
                *(uint32_t*)&hh[(ebase + r) * FFN + col] = hi;
                *(uint32_t*)&hl[(ebase + r) * FFN + col] = lo;
            }
        }
}

// ---- FFN2 step: warp tile 64m x 64n, 96 MMAs, 16 ldsm.x4 ----
static __device__ __forceinline__ void ffn2_step(uint32_t Sb, int ks, int wm, int wn, int lane,
                                                 float cd[4][8][4]) {
    const int g = lane >> 3;
    const int jrow = ((g >> 1) << 3) + (lane & 7);
    const int kofB = ks * 16 + ((g & 1) << 3);
    uint32_t bh[8][2], bl[8][2];
    #pragma unroll
    for (int j2 = 0; j2 < 4; j2++) {
        uint32_t nrow = (uint32_t)(wn * 64 + j2 * 16 + jrow);
        uint32_t bd = Sb + (uint32_t)((S2_BH + nrow * SROW + kofB) * 2);
        ldsm4(&bh[2 * j2][0], bd);
        ldsm4(&bl[2 * j2][0], bd + (S2_BL - S2_BH) * 2);
    }
    const int kofA = ks * 16 + ((lane >> 4) << 3);
    const int arow_b = wm * 64 + (lane & 15);
    #pragma unroll
    for (int i = 0; i < 4; i++) {
        uint32_t ah[4], al[4];
        uint32_t ad = Sb + (uint32_t)((S2_AH + (arow_b + i * 16) * SROW + kofA) * 2);
        ldsm4(ah, ad);
        ldsm4(al, ad + (S2_AL - S2_AH) * 2);
        #pragma unroll
        for (int j = 0; j < 8; j++) {
            mma16816(cd[i][j], ah, bh[j]);
            mma16816(cd[i][j], ah, bl[j]);
            mma16816(cd[i][j], al, bh[j]);
        }
    }
}

// ---------------- kernel 4: grouped GEMM2 (H @ w_down^T)*score -> Y --------
// CTA tile: 128 rows x 256 D-cols. Warps 2m x 4n (64x64).
__global__ void __launch_bounds__(256, 1) k_ffn2_mma(const float* __restrict__ wd) {
    extern __shared__ __align__(16) uint16_t sm[];
    const int e = blockIdx.z;
    const int cnt = min(g_counts[e], CAP);
    const int m0 = blockIdx.y * 128;
    if (m0 >= cnt) return;
    const int n0 = blockIdx.x * 256;
    const int tid = threadIdx.x;
    const uint32_t sbase = smem_u32(sm);

    const int arow = tid >> 1, ak = (tid & 1) * 16;
    const uint16_t* gah = (const uint16_t*)g_Hhi + ((size_t)e * CAP + m0 + arow) * FFN + ak;
    const uint16_t* gal = (const uint16_t*)g_Hlo + ((size_t)e * CAP + m0 + arow) * FFN + ak;
    const uint32_t sAoff = (uint32_t)(arow * SROW + ak) * 2;

    // B loader: one w_down row (D-col) per thread, 32 floats
    const float* gb = wd + (size_t)e * DIM * FFN + (size_t)(n0 + tid) * FFN;
    const uint32_t bidx = (uint32_t)(tid * SROW);

    const int wid = tid >> 5, lane = tid & 31;
    const int wm = wid >> 2, wn = wid & 3;
    const int fg = lane >> 2, ft = lane & 3;

    float cd[4][8][4] = {};
    float4 rb[8];

    {
        uint32_t d = sbase + sAoff;
        cpasync16(d, gah); cpasync16(d + 16, gah + 8);
        cpasync16(d + S2_AL * 2, gal); cpasync16(d + S2_AL * 2 + 16, gal + 8);
        CP_COMMIT();
        #pragma unroll
        for (int q = 0; q < 8; q++) rb[q] = *(const float4*)(gb + 4 * q);
        #pragma unroll
        for (int q = 0; q < 4; q++) {
            uint4 hi, lo;
            hilo8(rb[2 * q], rb[2 * q + 1], hi, lo);
            *(uint4*)&sm[S2_BH + bidx + 8 * q] = hi;
            *(uint4*)&sm[S2_BL + bidx + 8 * q] = lo;
        }
    }

    const int C = FFN / 32;
    for (int c = 0; c < C; c++) {
        const int st = c & 1;
        const uint32_t Sb = sbase + (uint32_t)st * (STAGE_H * 2);
        CP_WAIT0();
        __syncthreads();
        const bool more = (c + 1 < C);
        if (more) {
            const int kk = (c + 1) * 32;
            uint32_t d = sbase + (uint32_t)(st ^ 1) * (STAGE_H * 2) + sAoff;
            cpasync16(d, gah + kk); cpasync16(d + 16, gah + kk + 8);
            cpasync16(d + S2_AL * 2, gal + kk); cpasync16(d + S2_AL * 2 + 16, gal + kk + 8);
            CP_COMMIT();
            #pragma unroll
            for (int q = 0; q < 8; q++) rb[q] = *(const float4*)(gb + kk + 4 * q);
        }
        ffn2_step(Sb, 0, wm, wn, lane, cd);
        if (more) {
            uint16_t* Sn = sm + (st ^ 1) * STAGE_H;
            #pragma unroll
            for (int q = 0; q < 4; q++) {
                uint4 hi, lo;
                hilo8(rb[2 * q], rb[2 * q + 1], hi, lo);
                *(uint4*)&Sn[S2_BH + bidx + 8 * q] = hi;
                *(uint4*)&Sn[S2_BL + bidx + 8 * q] = lo;
            }
        }
        ffn2_step(Sb, 1, wm, wn, lane, cd);
    }

    // epilogue: y * score -> g_Y
    const size_t ebase = (size_t)e * CAP;
    #pragma unroll
    for (int i = 0; i < 4; i++) {
        const int r0 = m0 + wm * 64 + i * 16 + fg;
        #pragma unroll
        for (int h = 0; h < 2; h++) {
            const int r = r0 + h * 8;
            const float s = g_score[ebase + r];
            float* yrow = g_Y + (ebase + r) * DIM;
            #pragma unroll
            for (int j = 0; j < 8; j++) {
                const int col = n0 + wn * 64 + j * 8 + ft * 2;
                float2 o;
                o.x = cd[i][j][2 * h] * s;
                o.y = cd[i][j][2 * h + 1] * s;
                *(float2*)&yrow[col] = o;
            }
        }
    }
}

// ---------------- kernel 5: combine ----------------
__global__ void __launch_bounds__(256) k_combine(float* __restrict__ out) {
    int t = blockIdx.x;
    int tid = threadIdx.x;
    float4 a0 = make_float4(0.f, 0.f, 0.f, 0.f);
    float4 a1 = make_float4(0.f, 0.f, 0.f, 0.f);
    #pragma unroll
    for (int k = 0; k < TOPK; k++) {
        int loc = g_loc[t * TOPK + k];
        if (loc < 0) continue;
        const float4* y = (const float4*)(g_Y + (size_t)loc * DIM);
        float4 v0 = y[tid * 2], v1 = y[tid * 2 + 1];
        a0.x += v0.x; a0.y += v0.y; a0.z += v0.z; a0.w += v0.w;
        a1.x += v1.x; a1.y += v1.y; a1.z += v1.z; a1.w += v1.w;
    }
    float4* o = (float4*)(out + (size_t)t * DIM);
    o[tid * 2] = a0;
    o[tid * 2 + 1] = a1;
}

// ---------------- launch ----------------
extern "C" void kernel_launch(void* const* d_in, const int* in_sizes, int n_in,
                              void* d_out, int out_size) {
    const float* x  = (const float*)d_in[0];   // hidden_states [1,2048,2048]
    const float* gw = (const float*)d_in[1];   // gate_w  [64,2048]
    const float* wg = (const float*)d_in[2];   // w_gate  [64,768,2048]
    const float* wu = (const float*)d_in[3];   // w_up    [64,768,2048]
    const float* wd = (const float*)d_in[4];   // w_down  [64,2048,768]
    float* out = (float*)d_out;

    cudaFuncSetAttribute(k_ffn1_mma, cudaFuncAttributeMaxDynamicSharedMemorySize, SMEM_BYTES);
    cudaFuncSetAttribute(k_ffn2_mma, cudaFuncAttributeMaxDynamicSharedMemorySize, SMEM_BYTES);

    k_zero_counts<<<1, 64>>>();
    k_xsplit<<<(NTOK * DIM) / (256 * 8), 256>>>(x);
    k_gating<<<NTOK, 128>>>(x, gw);
    k_ffn1_mma<<<dim3(FFN / 128, CAP / 128, NEXP), 256, SMEM_BYTES>>>(wg, wu);
    k_ffn2_mma<<<dim3(DIM / 256, CAP / 128, NEXP), 256, SMEM_BYTES>>>(wd);
    k_combine<<<NTOK, 256>>>(out);
}